// round 5
// baseline (speedup 1.0000x reference)
#include <cuda_runtime.h>
#include <cstdint>

// Problem constants
#define N0 100000
#define N1 50000
#define N2 25000
#define N3 12500
#define E0 800000
#define E1 400000
#define E2 200000
#define D  256
#define MAXDEG 64
#define OVF_CAP 65536

// ---------------- scratch (device globals; no allocation allowed) ----------
__device__ float g_mean[N1 * D];
__device__ float g_h1[N1 * D];
__device__ float g_h2[N2 * D];
__device__ int   g_bcnt[N1];
__device__ int   g_bins[N1 * MAXDEG];
__device__ int2  g_ovf[OVF_CAP];
__device__ int   g_ovf_n;
__device__ int   g_is64;

// ---------------- dtype detection ------------------------------------------
__global__ void detect_kernel(const int* __restrict__ e) {
    if (blockIdx.x == 0 && threadIdx.x == 0) {
        int is64 = 1;
        for (int i = 1; i < 64; i += 2)
            if (e[i] != 0) is64 = 0;
        g_is64 = is64;
    }
}

// ---------------- zero degree counters ---------------------------------------
__global__ void zcnt_kernel(int* __restrict__ bcnt, int M) {
    int i = blockIdx.x * blockDim.x + threadIdx.x;
    if (i == 0) g_ovf_n = 0;
    if (i < M) bcnt[i] = 0;
}

// ---------------- edge binning ------------------------------------------------
__global__ void bin_kernel(const void* __restrict__ eraw, int E,
                           int* __restrict__ bcnt, int* __restrict__ bins) {
    int i = blockIdx.x * blockDim.x + threadIdx.x;
    if (i >= E) return;
    int s, d;
    if (g_is64) {
        const long long* e = (const long long*)eraw;
        s = (int)e[i];
        d = (int)e[(long long)E + i];
    } else {
        const int* e = (const int*)eraw;
        s = e[i];
        d = e[E + i];
    }
    int slot = atomicAdd(&bcnt[d], 1);
    if (slot < MAXDEG) {
        bins[d * MAXDEG + slot] = s;
    } else {
        int o = atomicAdd(&g_ovf_n, 1);
        if (o < OVF_CAP) g_ovf[o] = make_int2(s, d);
    }
}

// ---------------- gather-mean: one warp per dst, 2-edge unroll ----------------
__global__ void __launch_bounds__(256)
gather_kernel(const float* __restrict__ h,
              const int* __restrict__ bcnt,
              const int* __restrict__ bins,
              float* __restrict__ mean, int M) {
    int gw   = (blockIdx.x * blockDim.x + threadIdx.x) >> 5;
    int lane = threadIdx.x & 31;
    if (gw >= M) return;

    int deg = bcnt[gw];
    int nb  = min(deg, MAXDEG);

    int src0 = 0, src1 = 0;
    if (lane < nb)      src0 = bins[gw * MAXDEG + lane];
    if (lane + 32 < nb) src1 = bins[gw * MAXDEG + lane + 32];

    float4 p0 = make_float4(0.f, 0.f, 0.f, 0.f), p1 = p0;
    float4 q0 = p0, q1 = p0;

    int i = 0;
    for (; i + 1 < nb; i += 2) {
        int sa = (i < 32)     ? __shfl_sync(0xffffffffu, src0, i)
                              : __shfl_sync(0xffffffffu, src1, i - 32);
        int sb = (i + 1 < 32) ? __shfl_sync(0xffffffffu, src0, i + 1)
                              : __shfl_sync(0xffffffffu, src1, i - 31);
        const float4* ra = (const float4*)(h + (size_t)sa * D);
        const float4* rb = (const float4*)(h + (size_t)sb * D);
        float4 a0 = ra[lane], a1 = ra[lane + 32];
        float4 b0 = rb[lane], b1 = rb[lane + 32];
        p0.x += a0.x; p0.y += a0.y; p0.z += a0.z; p0.w += a0.w;
        p1.x += a1.x; p1.y += a1.y; p1.z += a1.z; p1.w += a1.w;
        q0.x += b0.x; q0.y += b0.y; q0.z += b0.z; q0.w += b0.w;
        q1.x += b1.x; q1.y += b1.y; q1.z += b1.z; q1.w += b1.w;
    }
    if (i < nb) {
        int sa = (i < 32) ? __shfl_sync(0xffffffffu, src0, i)
                          : __shfl_sync(0xffffffffu, src1, i - 32);
        const float4* ra = (const float4*)(h + (size_t)sa * D);
        float4 a0 = ra[lane], a1 = ra[lane + 32];
        p0.x += a0.x; p0.y += a0.y; p0.z += a0.z; p0.w += a0.w;
        p1.x += a1.x; p1.y += a1.y; p1.z += a1.z; p1.w += a1.w;
    }
    p0.x += q0.x; p0.y += q0.y; p0.z += q0.z; p0.w += q0.w;
    p1.x += q1.x; p1.y += q1.y; p1.z += q1.z; p1.w += q1.w;

    float r = 1.0f / fmaxf((float)deg, 1.0f);
    p0.x *= r; p0.y *= r; p0.z *= r; p0.w *= r;
    p1.x *= r; p1.y *= r; p1.z *= r; p1.w *= r;
    float4* out = (float4*)(mean + (size_t)gw * D);
    out[lane]      = p0;
    out[lane + 32] = p1;
}

// ---------------- overflow fixup (expected no-op) ------------------------------
__device__ __forceinline__ void red_add_v4(float* p, float4 v) {
    asm volatile("red.global.add.v4.f32 [%0], {%1,%2,%3,%4};"
                 :: "l"(p), "f"(v.x), "f"(v.y), "f"(v.z), "f"(v.w)
                 : "memory");
}

__global__ void ovf_fix_kernel(const float* __restrict__ h,
                               const int* __restrict__ bcnt,
                               float* __restrict__ mean) {
    int n = g_ovf_n;
    if (n == 0) return;
    if (n > OVF_CAP) n = OVF_CAP;
    int lane = threadIdx.x & 31;
    int wid  = (blockIdx.x * blockDim.x + threadIdx.x) >> 5;
    int nw   = (gridDim.x * blockDim.x) >> 5;
    for (int k = wid; k < n; k += nw) {
        int2 sd = g_ovf[k];
        float r = 1.0f / fmaxf((float)bcnt[sd.y], 1.0f);
        const float4* row = (const float4*)(h + (size_t)sd.x * D);
        float* dst = mean + (size_t)sd.y * D;
#pragma unroll
        for (int j = 0; j < 2; j++) {
            int idx = lane + 32 * j;
            float4 v = row[idx];
            v.x *= r; v.y *= r; v.z *= r; v.w *= r;
            red_add_v4(dst + idx * 4, v);
        }
    }
}

// ---------------- fused SAGE GEMM (TF32, 64x64 warp tile, double-buffered) ----
// C[m,:] = mean[m] @ Wl + h_dst[m] @ Wr + b   (optional ReLU)
// Block 128x128, 4 warps (2x2), warp tile 64x64, BK=16.
// Smem: float2-paired layout, pitch 20 f2 (conflict-free for frag reads).

#define PA 20
#define PB 20
#define ABUF (128 * PA)   // float2 count per A buffer
#define BBUF (128 * PB)

__device__ __forceinline__ unsigned f2tf(float f) {
    unsigned u;
    asm("cvt.rna.tf32.f32 %0, %1;" : "=r"(u) : "f"(f));
    return u;
}
__device__ __forceinline__ unsigned fu(float f) { return __float_as_uint(f); }
__device__ __forceinline__ float u2f(unsigned u) { return __uint_as_float(u); }

__device__ __forceinline__ void mma_tf32(float c[4], const unsigned a[4],
                                         unsigned b0, unsigned b1) {
    asm volatile(
        "mma.sync.aligned.m16n8k8.row.col.f32.tf32.tf32.f32 "
        "{%0,%1,%2,%3}, {%4,%5,%6,%7}, {%8,%9}, {%0,%1,%2,%3};"
        : "+f"(c[0]), "+f"(c[1]), "+f"(c[2]), "+f"(c[3])
        : "r"(a[0]), "r"(a[1]), "r"(a[2]), "r"(a[3]), "r"(b0), "r"(b1));
}

__global__ void __launch_bounds__(128, 2)
sage_gemm_tc(const float* __restrict__ A1,   // [M, 256] mean
             const float* __restrict__ A2,   // [M, 256] h_dst
             const float* __restrict__ Wl,
             const float* __restrict__ Wr,
             const float* __restrict__ bias,
             float* __restrict__ C,
             int M, int do_relu) {
    extern __shared__ float2 smem[];
    float2* As2 = smem;            // 2 * ABUF
    float2* Bs2 = smem + 2 * ABUF; // 2 * BBUF

    const int tid  = threadIdx.x;
    const int lane = tid & 31;
    const int warp = tid >> 5;     // 0..3
    const int wm   = warp >> 1;    // 0..1 -> m offset *64
    const int wn   = warp & 1;     // 0..1 -> n offset *64
    const int row0 = blockIdx.y * 128;
    const int col0 = blockIdx.x * 128;
    const int lr   = lane >> 2;
    const int lc   = lane & 3;

    // loader indices (128 threads)
    const int garow = row0 + tid;              // A row
    const int bk    = tid >> 3;                // 0..15 (k row of B tile)
    const int bn0   = (tid & 7) * 16;          // 16 n-cols
    const int bslot = (bk >> 3) * 4 + (bk & 3);
    const int belem = (bk & 7) >> 2;
    const int rot   = tid & 7;

    float va[16], wb[16];
    float acc[4][8][4];
#pragma unroll
    for (int mi = 0; mi < 4; mi++)
#pragma unroll
        for (int ni = 0; ni < 8; ni++)
#pragma unroll
            for (int j = 0; j < 4; j++) acc[mi][ni][j] = 0.0f;

    // it in [0,32): phase = it>>4, k0 = (it&15)*16
#define LOADG(it)                                                              \
    {                                                                          \
        const int phase_ = (it) >> 4;                                          \
        const int k0_    = ((it) & 15) << 4;                                   \
        const float* Ap = phase_ ? A2 : A1;                                    \
        const float* Bp = phase_ ? Wr : Wl;                                    \
        if (garow < M) {                                                       \
            const float4* ap = (const float4*)(Ap + (size_t)garow * D + k0_);  \
            *(float4*)&va[0]  = ap[0];                                         \
            *(float4*)&va[4]  = ap[1];                                         \
            *(float4*)&va[8]  = ap[2];                                         \
            *(float4*)&va[12] = ap[3];                                         \
        } else {                                                               \
            _Pragma("unroll") for (int j = 0; j < 16; j++) va[j] = 0.0f;       \
        }                                                                      \
        const float4* bp = (const float4*)(Bp + (size_t)(k0_ + bk) * D + col0 + bn0); \
        *(float4*)&wb[0]  = bp[0];                                             \
        *(float4*)&wb[4]  = bp[1];                                             \
        *(float4*)&wb[8]  = bp[2];                                             \
        *(float4*)&wb[12] = bp[3];                                             \
    }

#define STORES(buf)                                                            \
    {                                                                          \
        float2* as_ = As2 + (buf)*ABUF;                                        \
        float2* bs_ = Bs2 + (buf)*BBUF;                                        \
        _Pragma("unroll") for (int jj = 0; jj < 8; jj++) {                     \
            int j = (jj + rot) & 7;                                            \
            int c = (j & 3) + ((j >> 2) << 3);                                 \
            as_[tid * PA + j] = make_float2(u2f(f2tf(va[c])),                  \
                                            u2f(f2tf(va[c + 4])));             \
        }                                                                      \
        _Pragma("unroll") for (int jj = 0; jj < 16; jj++) {                    \
            int j = (jj + rot) & 15;                                           \
            ((float*)&bs_[(bn0 + j) * PB + bslot])[belem] =                    \
                u2f(f2tf(wb[j]));                                              \
        }                                                                      \
    }

#define COMPUTE(buf)                                                           \
    {                                                                          \
        const float2* as_ = As2 + (buf)*ABUF;                                  \
        const float2* bs_ = Bs2 + (buf)*BBUF;                                  \
        _Pragma("unroll") for (int ks = 0; ks < 2; ks++) {                     \
            const int slot = ks * 4 + lc;                                      \
            unsigned a[4][4];                                                  \
            _Pragma("unroll") for (int mi = 0; mi < 4; mi++) {                 \
                int rb = wm * 64 + mi * 16 + lr;                               \
                float2 lo = as_[rb * PA + slot];                               \
                float2 hi = as_[(rb + 8) * PA + slot];                         \
                a[mi][0] = fu(lo.x); a[mi][1] = fu(hi.x);                      \
                a[mi][2] = fu(lo.y); a[mi][3] = fu(hi.y);                      \
            }                                                                  \
            _Pragma("unroll") for (int ni = 0; ni < 8; ni++) {                 \
                int nb = wn * 64 + ni * 8 + lr;                                \
                float2 b = bs_[nb * PB + slot];                                \
                unsigned b0 = fu(b.x), b1 = fu(b.y);                           \
                _Pragma("unroll") for (int mi = 0; mi < 4; mi++)               \
                    mma_tf32(acc[mi][ni], a[mi], b0, b1);                      \
            }                                                                  \
        }                                                                      \
    }

    LOADG(0);
    STORES(0);
    __syncthreads();

    for (int it = 0; it < 32; it++) {
        if (it < 31) LOADG(it + 1);
        COMPUTE(it & 1);
        if (it < 31) STORES((it + 1) & 1);
        __syncthreads();
    }

    // epilogue
#pragma unroll
    for (int mi = 0; mi < 4; mi++) {
        const int r = row0 + wm * 64 + mi * 16 + lr;
#pragma unroll
        for (int ni = 0; ni < 8; ni++) {
            const int cidx = col0 + wn * 64 + ni * 8 + lc * 2;
            const float bb0 = bias[cidx];
            const float bb1 = bias[cidx + 1];
            float v0 = acc[mi][ni][0] + bb0;
            float v1 = acc[mi][ni][1] + bb1;
            float v2 = acc[mi][ni][2] + bb0;
            float v3 = acc[mi][ni][3] + bb1;
            if (do_relu) {
                v0 = fmaxf(v0, 0.f); v1 = fmaxf(v1, 0.f);
                v2 = fmaxf(v2, 0.f); v3 = fmaxf(v3, 0.f);
            }
            if (r < M) {
                C[(size_t)r * D + cidx]     = v0;
                C[(size_t)r * D + cidx + 1] = v1;
            }
            if (r + 8 < M) {
                C[(size_t)(r + 8) * D + cidx]     = v2;
                C[(size_t)(r + 8) * D + cidx + 1] = v3;
            }
        }
    }
}

#define GEMM_SMEM (2 * (ABUF + BBUF) * (int)sizeof(float2))

// ---------------- launch -----------------------------------------------------
extern "C" void kernel_launch(void* const* d_in, const int* in_sizes, int n_in,
                              void* d_out, int out_size) {
    const float* x   = (const float*)d_in[0];
    const void*  e0  = d_in[1];
    const void*  e1  = d_in[2];
    const void*  e2  = d_in[3];
    const float* Wl0 = (const float*)d_in[4];
    const float* b0  = (const float*)d_in[5];
    const float* Wr0 = (const float*)d_in[6];
    const float* Wl1 = (const float*)d_in[7];
    const float* b1  = (const float*)d_in[8];
    const float* Wr1 = (const float*)d_in[9];
    const float* Wl2 = (const float*)d_in[10];
    const float* b2  = (const float*)d_in[11];
    const float* Wr2 = (const float*)d_in[12];
    float* out = (float*)d_out;

    float *mean, *h1, *h2;
    int *bcnt, *bins;
    cudaGetSymbolAddress((void**)&mean, g_mean);
    cudaGetSymbolAddress((void**)&h1,   g_h1);
    cudaGetSymbolAddress((void**)&h2,   g_h2);
    cudaGetSymbolAddress((void**)&bcnt, g_bcnt);
    cudaGetSymbolAddress((void**)&bins, g_bins);

    cudaFuncSetAttribute(sage_gemm_tc,
                         cudaFuncAttributeMaxDynamicSharedMemorySize, GEMM_SMEM);

    detect_kernel<<<1, 32>>>((const int*)e0);

    // ---- layer 0: x[N0] -> h1[N1]
    zcnt_kernel<<<(N1 + 255) / 256, 256>>>(bcnt, N1);
    bin_kernel<<<(E0 + 255) / 256, 256>>>(e0, E0, bcnt, bins);
    gather_kernel<<<(N1 * 32 + 255) / 256, 256>>>(x, bcnt, bins, mean, N1);
    ovf_fix_kernel<<<2, 256>>>(x, bcnt, mean);
    sage_gemm_tc<<<dim3(2, (N1 + 127) / 128), 128, GEMM_SMEM>>>(
        mean, x, Wl0, Wr0, b0, h1, N1, 1);

    // ---- layer 1: h1[N1] -> h2[N2]
    zcnt_kernel<<<(N2 + 255) / 256, 256>>>(bcnt, N2);
    bin_kernel<<<(E1 + 255) / 256, 256>>>(e1, E1, bcnt, bins);
    gather_kernel<<<(N2 * 32 + 255) / 256, 256>>>(h1, bcnt, bins, mean, N2);
    ovf_fix_kernel<<<2, 256>>>(h1, bcnt, mean);
    sage_gemm_tc<<<dim3(2, (N2 + 127) / 128), 128, GEMM_SMEM>>>(
        mean, h1, Wl1, Wr1, b1, h2, N2, 1);

    // ---- layer 2: h2[N2] -> out[N3] (no ReLU)
    zcnt_kernel<<<(N3 + 255) / 256, 256>>>(bcnt, N3);
    bin_kernel<<<(E2 + 255) / 256, 256>>>(e2, E2, bcnt, bins);
    gather_kernel<<<(N3 * 32 + 255) / 256, 256>>>(h2, bcnt, bins, mean, N3);
    ovf_fix_kernel<<<2, 256>>>(h2, bcnt, mean);
    sage_gemm_tc<<<dim3(2, (N3 + 127) / 128), 128, GEMM_SMEM>>>(
        mean, h2, Wl2, Wr2, b2, out, N3, 0);
}

// round 6
// speedup vs baseline: 2.1376x; 2.1376x over previous
#include <cuda_runtime.h>
#include <cstdint>

// Problem constants
#define N0 100000
#define N1 50000
#define N2 25000
#define N3 12500
#define E0 800000
#define E1 400000
#define E2 200000
#define D  256
#define MAXDEG 64
#define OVF_CAP 65536

// ---------------- scratch (device globals; no allocation allowed) ----------
__device__ float g_mean[N1 * D];
__device__ float g_h1[N1 * D];
__device__ float g_h2[N2 * D];
__device__ int   g_bcnt[N1];
__device__ int   g_bins[N1 * MAXDEG];
__device__ int2  g_ovf[OVF_CAP];
__device__ int   g_ovf_n;
__device__ int   g_is64;

// ---------------- dtype detection ------------------------------------------
__global__ void detect_kernel(const int* __restrict__ e) {
    if (blockIdx.x == 0 && threadIdx.x == 0) {
        int is64 = 1;
        for (int i = 1; i < 64; i += 2)
            if (e[i] != 0) is64 = 0;
        g_is64 = is64;
    }
}

// ---------------- zero degree counters ---------------------------------------
__global__ void zcnt_kernel(int* __restrict__ bcnt, int M) {
    int i = blockIdx.x * blockDim.x + threadIdx.x;
    if (i == 0) g_ovf_n = 0;
    if (i < M) bcnt[i] = 0;
}

// ---------------- edge binning ------------------------------------------------
__global__ void bin_kernel(const void* __restrict__ eraw, int E,
                           int* __restrict__ bcnt, int* __restrict__ bins) {
    int i = blockIdx.x * blockDim.x + threadIdx.x;
    if (i >= E) return;
    int s, d;
    if (g_is64) {
        const long long* e = (const long long*)eraw;
        s = (int)e[i];
        d = (int)e[(long long)E + i];
    } else {
        const int* e = (const int*)eraw;
        s = e[i];
        d = e[E + i];
    }
    int slot = atomicAdd(&bcnt[d], 1);
    if (slot < MAXDEG) {
        bins[d * MAXDEG + slot] = s;
    } else {
        int o = atomicAdd(&g_ovf_n, 1);
        if (o < OVF_CAP) g_ovf[o] = make_int2(s, d);
    }
}

// ---------------- gather-mean: one warp per dst row (R4 exact) ----------------
__global__ void __launch_bounds__(256)
gather_kernel(const float* __restrict__ h,
              const int* __restrict__ bcnt,
              const int* __restrict__ bins,
              float* __restrict__ mean, int M) {
    int gw   = (blockIdx.x * blockDim.x + threadIdx.x) >> 5;
    int lane = threadIdx.x & 31;
    if (gw >= M) return;

    int deg = bcnt[gw];
    int nb  = min(deg, MAXDEG);

    int src0 = 0, src1 = 0;
    if (lane < nb)      src0 = bins[gw * MAXDEG + lane];
    if (lane + 32 < nb) src1 = bins[gw * MAXDEG + lane + 32];

    float4 acc0 = make_float4(0.f, 0.f, 0.f, 0.f);
    float4 acc1 = make_float4(0.f, 0.f, 0.f, 0.f);

    for (int i = 0; i < nb; i++) {
        int s = (i < 32) ? __shfl_sync(0xffffffffu, src0, i)
                         : __shfl_sync(0xffffffffu, src1, i - 32);
        const float4* row = (const float4*)(h + (size_t)s * D);
        float4 a = row[lane];
        float4 b = row[lane + 32];
        acc0.x += a.x; acc0.y += a.y; acc0.z += a.z; acc0.w += a.w;
        acc1.x += b.x; acc1.y += b.y; acc1.z += b.z; acc1.w += b.w;
    }

    float r = 1.0f / fmaxf((float)deg, 1.0f);
    float4* out = (float4*)(mean + (size_t)gw * D);
    acc0.x *= r; acc0.y *= r; acc0.z *= r; acc0.w *= r;
    acc1.x *= r; acc1.y *= r; acc1.z *= r; acc1.w *= r;
    out[lane]      = acc0;
    out[lane + 32] = acc1;
}

// ---------------- overflow fixup (expected no-op) ------------------------------
__device__ __forceinline__ void red_add_v4(float* p, float4 v) {
    asm volatile("red.global.add.v4.f32 [%0], {%1,%2,%3,%4};"
                 :: "l"(p), "f"(v.x), "f"(v.y), "f"(v.z), "f"(v.w)
                 : "memory");
}

__global__ void ovf_fix_kernel(const float* __restrict__ h,
                               const int* __restrict__ bcnt,
                               float* __restrict__ mean) {
    int n = g_ovf_n;
    if (n == 0) return;
    if (n > OVF_CAP) n = OVF_CAP;
    int lane = threadIdx.x & 31;
    int wid  = (blockIdx.x * blockDim.x + threadIdx.x) >> 5;
    int nw   = (gridDim.x * blockDim.x) >> 5;
    for (int k = wid; k < n; k += nw) {
        int2 sd = g_ovf[k];
        float r = 1.0f / fmaxf((float)bcnt[sd.y], 1.0f);
        const float4* row = (const float4*)(h + (size_t)sd.x * D);
        float* dst = mean + (size_t)sd.y * D;
#pragma unroll
        for (int j = 0; j < 2; j++) {
            int idx = lane + 32 * j;
            float4 v = row[idx];
            v.x *= r; v.y *= r; v.z *= r; v.w *= r;
            red_add_v4(dst + idx * 4, v);
        }
    }
}

// ---------------- fused SAGE GEMM (TF32, R2 layout + double buffering) --------
// C[m,:] = mean[m] @ Wl + h_dst[m] @ Wr + b   (optional ReLU)
// Block 128x128, 8 warps (4x2), warp tile 32x64, BK=16.
// Same As/Bs layout and fragment addressing as the validated R2 kernel;
// only change: 2-deep smem ring + register-staged prefetch, 1 sync/chunk.

#define AS_STRIDE 20
#define BS_STRIDE 136
#define ABUF (128 * AS_STRIDE)
#define BBUF (16 * BS_STRIDE)

__device__ __forceinline__ unsigned f2tf(float f) {
    unsigned u;
    asm("cvt.rna.tf32.f32 %0, %1;" : "=r"(u) : "f"(f));
    return u;
}
__device__ __forceinline__ unsigned fu(float f) { return __float_as_uint(f); }

__device__ __forceinline__ void mma_tf32(float c[4], const unsigned a[4],
                                         unsigned b0, unsigned b1) {
    asm volatile(
        "mma.sync.aligned.m16n8k8.row.col.f32.tf32.tf32.f32 "
        "{%0,%1,%2,%3}, {%4,%5,%6,%7}, {%8,%9}, {%0,%1,%2,%3};"
        : "+f"(c[0]), "+f"(c[1]), "+f"(c[2]), "+f"(c[3])
        : "r"(a[0]), "r"(a[1]), "r"(a[2]), "r"(a[3]), "r"(b0), "r"(b1));
}

__global__ void __launch_bounds__(256, 2)
sage_gemm_tc(const float* __restrict__ A1,   // [M, 256] mean
             const float* __restrict__ A2,   // [M, 256] h_dst
             const float* __restrict__ Wl,
             const float* __restrict__ Wr,
             const float* __restrict__ bias,
             float* __restrict__ C,
             int M, int do_relu) {
    __shared__ float As[2 * ABUF];
    __shared__ float Bs[2 * BBUF];

    const int tid  = threadIdx.x;
    const int lane = tid & 31;
    const int warp = tid >> 5;
    const int wm   = warp >> 1;
    const int wn   = warp & 1;
    const int row0 = blockIdx.y * 128;
    const int col0 = blockIdx.x * 128;

    const int arow_l = tid >> 1;
    const int akslot = (tid & 1) * 8;
    const int brow_l = tid >> 4;
    const int bcol_l = (tid & 15) * 8;

    const int garow = row0 + arow_l;

    float acc[2][8][4];
#pragma unroll
    for (int mi = 0; mi < 2; mi++)
#pragma unroll
        for (int ni = 0; ni < 8; ni++)
#pragma unroll
            for (int j = 0; j < 4; j++) acc[mi][ni][j] = 0.0f;

    const int lr = lane >> 2;
    const int lc = lane & 3;

    float va[8], wb[8];

    // it in [0,32): phase = it>>4, k0 = (it&15)*16
#define LOADG(it)                                                              \
    {                                                                          \
        const int phase_ = (it) >> 4;                                          \
        const int k0_    = ((it) & 15) << 4;                                   \
        const float* Ap = phase_ ? A2 : A1;                                    \
        const float* Bp = phase_ ? Wr : Wl;                                    \
        if (garow < M) {                                                       \
            const float4* ap = (const float4*)(Ap + (size_t)garow * D + k0_ + akslot); \
            *(float4*)&va[0] = ap[0];                                          \
            *(float4*)&va[4] = ap[1];                                          \
        } else {                                                               \
            _Pragma("unroll") for (int j = 0; j < 8; j++) va[j] = 0.0f;        \
        }                                                                      \
        const float4* bp = (const float4*)(Bp + (size_t)(k0_ + brow_l) * D + col0 + bcol_l); \
        *(float4*)&wb[0] = bp[0];                                              \
        *(float4*)&wb[4] = bp[1];                                              \
    }

#define STORES(buf)                                                            \
    {                                                                          \
        float* as_ = &As[(buf) * ABUF + arow_l * AS_STRIDE + akslot];          \
        float* bs_ = &Bs[(buf) * BBUF + brow_l * BS_STRIDE + bcol_l];          \
        _Pragma("unroll") for (int j = 0; j < 8; j++)                          \
            as_[j] = __uint_as_float(f2tf(va[j]));                             \
        _Pragma("unroll") for (int j = 0; j < 8; j++)                          \
            bs_[j] = __uint_as_float(f2tf(wb[j]));                             \
    }

#define COMPUTE(buf)                                                           \
    {                                                                          \
        const float* as_ = &As[(buf) * ABUF];                                  \
        const float* bs_ = &Bs[(buf) * BBUF];                                  \
        _Pragma("unroll") for (int ks = 0; ks < 2; ks++) {                     \
            const int k8 = ks * 8;                                             \
            unsigned a[2][4];                                                  \
            _Pragma("unroll") for (int mi = 0; mi < 2; mi++) {                 \
                const int rb = wm * 32 + mi * 16 + lr;                         \
                a[mi][0] = fu(as_[rb * AS_STRIDE + k8 + lc]);                  \
                a[mi][1] = fu(as_[(rb + 8) * AS_STRIDE + k8 + lc]);            \
                a[mi][2] = fu(as_[rb * AS_STRIDE + k8 + lc + 4]);              \
                a[mi][3] = fu(as_[(rb + 8) * AS_STRIDE + k8 + lc + 4]);        \
            }                                                                  \
            _Pragma("unroll") for (int ni = 0; ni < 8; ni++) {                 \
                const int nb = wn * 64 + ni * 8 + lr;                          \
                unsigned b0 = fu(bs_[(k8 + lc) * BS_STRIDE + nb]);             \
                unsigned b1 = fu(bs_[(k8 + lc + 4) * BS_STRIDE + nb]);         \
                mma_tf32(acc[0][ni], a[0], b0, b1);                            \
                mma_tf32(acc[1][ni], a[1], b0, b1);                            \
            }                                                                  \
        }                                                                      \
    }

    LOADG(0);
    STORES(0);
    __syncthreads();

    for (int it = 0; it < 32; it++) {
        if (it < 31) LOADG(it + 1);
        COMPUTE(it & 1);
        if (it < 31) STORES((it + 1) & 1);
        __syncthreads();
    }

    // epilogue
#pragma unroll
    for (int mi = 0; mi < 2; mi++) {
        const int r = row0 + wm * 32 + mi * 16 + lr;
#pragma unroll
        for (int ni = 0; ni < 8; ni++) {
            const int cidx = col0 + wn * 64 + ni * 8 + lc * 2;
            const float bb0 = bias[cidx];
            const float bb1 = bias[cidx + 1];
            float v0 = acc[mi][ni][0] + bb0;
            float v1 = acc[mi][ni][1] + bb1;
            float v2 = acc[mi][ni][2] + bb0;
            float v3 = acc[mi][ni][3] + bb1;
            if (do_relu) {
                v0 = fmaxf(v0, 0.f); v1 = fmaxf(v1, 0.f);
                v2 = fmaxf(v2, 0.f); v3 = fmaxf(v3, 0.f);
            }
            if (r < M) {
                C[(size_t)r * D + cidx]     = v0;
                C[(size_t)r * D + cidx + 1] = v1;
            }
            if (r + 8 < M) {
                C[(size_t)(r + 8) * D + cidx]     = v2;
                C[(size_t)(r + 8) * D + cidx + 1] = v3;
            }
        }
    }
}

// ---------------- launch -----------------------------------------------------
extern "C" void kernel_launch(void* const* d_in, const int* in_sizes, int n_in,
                              void* d_out, int out_size) {
    const float* x   = (const float*)d_in[0];
    const void*  e0  = d_in[1];
    const void*  e1  = d_in[2];
    const void*  e2  = d_in[3];
    const float* Wl0 = (const float*)d_in[4];
    const float* b0  = (const float*)d_in[5];
    const float* Wr0 = (const float*)d_in[6];
    const float* Wl1 = (const float*)d_in[7];
    const float* b1  = (const float*)d_in[8];
    const float* Wr1 = (const float*)d_in[9];
    const float* Wl2 = (const float*)d_in[10];
    const float* b2  = (const float*)d_in[11];
    const float* Wr2 = (const float*)d_in[12];
    float* out = (float*)d_out;

    float *mean, *h1, *h2;
    int *bcnt, *bins;
    cudaGetSymbolAddress((void**)&mean, g_mean);
    cudaGetSymbolAddress((void**)&h1,   g_h1);
    cudaGetSymbolAddress((void**)&h2,   g_h2);
    cudaGetSymbolAddress((void**)&bcnt, g_bcnt);
    cudaGetSymbolAddress((void**)&bins, g_bins);

    detect_kernel<<<1, 32>>>((const int*)e0);

    // ---- layer 0: x[N0] -> h1[N1]
    zcnt_kernel<<<(N1 + 255) / 256, 256>>>(bcnt, N1);
    bin_kernel<<<(E0 + 255) / 256, 256>>>(e0, E0, bcnt, bins);
    gather_kernel<<<(N1 * 32 + 255) / 256, 256>>>(x, bcnt, bins, mean, N1);
    ovf_fix_kernel<<<2, 256>>>(x, bcnt, mean);
    sage_gemm_tc<<<dim3(2, (N1 + 127) / 128), 256>>>(
        mean, x, Wl0, Wr0, b0, h1, N1, 1);

    // ---- layer 1: h1[N1] -> h2[N2]
    zcnt_kernel<<<(N2 + 255) / 256, 256>>>(bcnt, N2);
    bin_kernel<<<(E1 + 255) / 256, 256>>>(e1, E1, bcnt, bins);
    gather_kernel<<<(N2 * 32 + 255) / 256, 256>>>(h1, bcnt, bins, mean, N2);
    ovf_fix_kernel<<<2, 256>>>(h1, bcnt, mean);
    sage_gemm_tc<<<dim3(2, (N2 + 127) / 128), 256>>>(
        mean, h1, Wl1, Wr1, b1, h2, N2, 1);

    // ---- layer 2: h2[N2] -> out[N3] (no ReLU)
    zcnt_kernel<<<(N3 + 255) / 256, 256>>>(bcnt, N3);
    bin_kernel<<<(E2 + 255) / 256, 256>>>(e2, E2, bcnt, bins);
    gather_kernel<<<(N3 * 32 + 255) / 256, 256>>>(h2, bcnt, bins, mean, N3);
    ovf_fix_kernel<<<2, 256>>>(h2, bcnt, mean);
    sage_gemm_tc<<<dim3(2, (N3 + 127) / 128), 256>>>(
        mean, h2, Wl2, Wr2, b2, out, N3, 0);
}